// round 9
// baseline (speedup 1.0000x reference)
#include <cuda_runtime.h>
#include <cstdint>

// ---------------- problem constants ----------------
#define W_IMG 512
#define H_IMG 512
#define CCH   3
#define BATCH 32
#define KSZ   32
#define PAD_LO 15            // SAME padding, even kernel: lo=15, hi=16

#define NTH   128            // 4 warps
#define MSEG  128            // rows per segment (2 segments per CTA -> M=256)
#define YHALF 2              // 512 / 256
#define NBLOCKS (YHALF * W_IMG * CCH)         // 3072
#define N_PRED ((size_t)BATCH * W_IMG * H_IMG * CCH)

// smem union (u32 units):
//   staging buf p: raw[288] @ RAW_OFF(p) (256 outputs + 31 halo, padded),
//                  B tf32 [32 k rows x pitch 40] @ B_OFF(p)
//   epilogue:      s_d [32 n x pitch 132], reuses same storage
#define RAWLEN 288
#define BPITCH 40
#define BUFLEN (RAWLEN + KSZ * BPITCH)   // 1568
#define RAW_OFF(p) ((p) * BUFLEN)
#define B_OFF(p)   ((p) * BUFLEN + RAWLEN)
#define DPITCH 132
#define SMEM_U32 (BATCH * DPITCH)        // 4224 >= 2*BUFLEN (3136)

__device__ double       g_partials[NBLOCKS];
__device__ unsigned int g_done = 0;

static __device__ __forceinline__ uint32_t f2tf(float v) {
    uint32_t r;
    asm("cvt.rna.tf32.f32 %0, %1;" : "=r"(r) : "f"(v));
    return r;
}

// D(16x8,f32) += A(16x8,tf32,row) * B(8x8,tf32,col)
static __device__ __forceinline__ void mma_tf32(float* d,
                                                uint32_t a0, uint32_t a1,
                                                uint32_t a2, uint32_t a3,
                                                uint32_t b0, uint32_t b1) {
    asm volatile(
        "mma.sync.aligned.m16n8k8.row.col.f32.tf32.tf32.f32 "
        "{%0,%1,%2,%3}, {%4,%5,%6,%7}, {%8,%9}, {%0,%1,%2,%3};"
        : "+f"(d[0]), "+f"(d[1]), "+f"(d[2]), "+f"(d[3])
        : "r"(a0), "r"(a1), "r"(a2), "r"(a3), "r"(b0), "r"(b1));
}

__global__ __launch_bounds__(NTH, 4)
void conv_mma_kernel(const float* __restrict__ img,
                     const float* __restrict__ psf,
                     const float* __restrict__ obs,
                     float* __restrict__ out,
                     long long loss_idx)
{
    __shared__ uint32_t s_u[SMEM_U32];
    __shared__ float  s_red[NTH / 32];
    __shared__ double s_dred[NTH / 32];
    __shared__ int    s_last;

    const int tid   = threadIdx.x;
    const int wid   = tid >> 5;
    const int lane  = tid & 31;
    const int yh    = blockIdx.x;        // which 256-row half
    const int x     = blockIdx.y;
    const int c     = blockIdx.z;
    const int ybase = yh * (2 * MSEG);

    const int g  = lane >> 2;            // fragment row
    const int t4 = lane & 3;             // fragment col/k

    // accumulators: [seg][mt][nt][4] ; warp w owns rows 32w..32w+31 of each segment
    float d[2][2][4][4];
#pragma unroll
    for (int sg = 0; sg < 2; ++sg)
#pragma unroll
        for (int mt = 0; mt < 2; ++mt)
#pragma unroll
            for (int nt = 0; nt < 4; ++nt)
#pragma unroll
                for (int i = 0; i < 4; ++i) d[sg][mt][nt][i] = 0.f;

    // ---- staging load (gmem -> regs) for PSF row r ----
    float rv0, rv1, rv2, bv[8];
    auto load_stage = [&](int r) {
        const int gx = x + r - PAD_LO;
        rv0 = 0.f; rv1 = 0.f; rv2 = 0.f;
        if ((unsigned)gx < W_IMG) {
            const float* rowp = img + ((size_t)gx * H_IMG) * CCH + c;
            int gy0 = ybase - PAD_LO + tid;
            int gy1 = gy0 + NTH;
            int gy2 = gy0 + 2 * NTH;
            if ((unsigned)gy0 < H_IMG) rv0 = rowp[(size_t)gy0 * CCH];
            if ((unsigned)gy1 < H_IMG) rv1 = rowp[(size_t)gy1 * CCH];
            if (tid + 2 * NTH < RAWLEN && (unsigned)gy2 < H_IMG)
                rv2 = rowp[(size_t)gy2 * CCH];
        }
#pragma unroll
        for (int j = 0; j < 8; ++j) {
            int e = tid + j * NTH;
            int b = e >> 5, s = e & 31;
            bv[j] = psf[((size_t)(b * KSZ + r) * KSZ + s) * CCH + c];
        }
    };
    auto store_stage = [&](int p) {
        uint32_t* raw = s_u + RAW_OFF(p);
        uint32_t* Bs  = s_u + B_OFF(p);
        raw[tid]           = f2tf(rv0);
        raw[tid + NTH]     = f2tf(rv1);
        if (tid + 2 * NTH < RAWLEN) raw[tid + 2 * NTH] = f2tf(rv2);
#pragma unroll
        for (int j = 0; j < 8; ++j) {
            int e = tid + j * NTH;
            int b = e >> 5, s = e & 31;
            Bs[s * BPITCH + b] = f2tf(bv[j]);   // [k=s][n=b], conflict-free reads
        }
    };

    load_stage(0);
    store_stage(0);
    __syncthreads();

    const int abase = 32 * wid + g + t4;

    // ---------------- main loop over PSF rows ----------------
#pragma unroll 1
    for (int r = 0; r < KSZ; ++r) {
        if (r + 1 < KSZ) load_stage(r + 1);     // LDGs early

        const uint32_t* raw = s_u + RAW_OFF(r & 1);
        const uint32_t* Bs  = s_u + B_OFF(r & 1);

        // Toeplitz A register cache: 14 distinct words per segment
        uint32_t rv[2][14];
#pragma unroll
        for (int t = 0; t < 14; ++t) {
            rv[0][t] = raw[abase + 4 * t];
            rv[1][t] = raw[abase + 4 * t + MSEG];
        }

        const int bbase = t4 * BPITCH + g;
#pragma unroll
        for (int k8 = 0; k8 < 4; ++k8) {
            uint32_t b0[4], b1[4];
#pragma unroll
            for (int nt = 0; nt < 4; ++nt) {
                const int off = bbase + k8 * 8 * BPITCH + nt * 8;
                b0[nt] = Bs[off];
                b1[nt] = Bs[off + 4 * BPITCH];
            }
#pragma unroll
            for (int sg = 0; sg < 2; ++sg)
#pragma unroll
                for (int mt = 0; mt < 2; ++mt) {
                    const int t0 = 4 * mt + 2 * k8;
                    const uint32_t a0 = rv[sg][t0];
                    const uint32_t a1 = rv[sg][t0 + 2];
                    const uint32_t a2 = rv[sg][t0 + 1];
                    const uint32_t a3 = rv[sg][t0 + 3];
#pragma unroll
                    for (int nt = 0; nt < 4; ++nt)
                        mma_tf32(d[sg][mt][nt], a0, a1, a2, a3, b0[nt], b1[nt]);
                }
        }

        if (r + 1 < KSZ) store_stage((r + 1) & 1);
        __syncthreads();
    }

    // ---------------- epilogue: per segment, transpose -> gmem + loss ----------------
    float lsum = 0.f;
#pragma unroll 1
    for (int sg = 0; sg < 2; ++sg) {
#pragma unroll
        for (int mt = 0; mt < 2; ++mt)
#pragma unroll
            for (int nt = 0; nt < 4; ++nt)
#pragma unroll
                for (int i = 0; i < 4; ++i) {
                    const int n = nt * 8 + 2 * t4 + (i & 1);
                    const int y = 32 * wid + 16 * mt + g + ((i >> 1) ? 8 : 0);
                    s_u[n * DPITCH + y] = __float_as_uint(d[sg][mt][nt][i]);
                }
        __syncthreads();

        const int bb = tid >> 2;
        const int yq = tid & 3;
        const uint32_t* drow = s_u + bb * DPITCH + yq * 32;
        const int y0 = ybase + sg * MSEG + yq * 32;
        const size_t obase =
            ((size_t)((size_t)bb * W_IMG + x) * H_IMG + y0) * CCH + c;
#pragma unroll
        for (int i = 0; i < 32; ++i) {
            float p = __uint_as_float(drow[i]);
            size_t idx = obase + (size_t)i * CCH;
            out[idx] = p;
            float dd = obs[idx] - p;
            lsum += dd * dd;
        }
        __syncthreads();
    }

    // block reduce loss
#pragma unroll
    for (int off = 16; off; off >>= 1)
        lsum += __shfl_xor_sync(0xffffffffu, lsum, off);
    if (lane == 0) s_red[wid] = lsum;
    __syncthreads();

    const int lin = yh + YHALF * (x + W_IMG * c);
    if (tid == 0) {
        float bsum = 0.f;
#pragma unroll
        for (int w = 0; w < NTH / 32; ++w) bsum += s_red[w];
        g_partials[lin] = (double)bsum;
        __threadfence();
        unsigned prev = atomicAdd(&g_done, 1u);
        s_last = (prev == NBLOCKS - 1);
    }
    __syncthreads();

    if (s_last) {
        double dsum = 0.0;
        for (int i = tid; i < NBLOCKS; i += NTH) dsum += g_partials[i];
#pragma unroll
        for (int off = 16; off; off >>= 1)
            dsum += __shfl_xor_sync(0xffffffffu, dsum, off);
        if (lane == 0) s_dred[wid] = dsum;
        __syncthreads();
        if (tid == 0) {
            double tot = 0.0;
#pragma unroll
            for (int w = 0; w < NTH / 32; ++w) tot += s_dred[w];
            out[loss_idx] = (float)(tot / (double)N_PRED);
            g_done = 0;   // self-reset: deterministic across graph replays
        }
    }
}

extern "C" void kernel_launch(void* const* d_in, const int* in_sizes, int n_in,
                              void* d_out, int out_size) {
    const float* obs = nullptr;
    const float* img = nullptr;
    const float* psf = nullptr;
    for (int i = 0; i < n_in; ++i) {
        long long n = in_sizes[i];
        if (n == (long long)BATCH * W_IMG * H_IMG * CCH)      obs = (const float*)d_in[i];
        else if (n == (long long)W_IMG * H_IMG * CCH)         img = (const float*)d_in[i];
        else if (n == (long long)BATCH * KSZ * KSZ * CCH)     psf = (const float*)d_in[i];
    }
    float* out = (float*)d_out;

    dim3 grid(YHALF, W_IMG, CCH);   // 3072 CTAs
    conv_mma_kernel<<<grid, NTH>>>(img, psf, obs, out, (long long)out_size - 1);
}

// round 10
// speedup vs baseline: 1.2721x; 1.2721x over previous
#include <cuda_runtime.h>
#include <cstdint>

// ---------------- problem constants ----------------
#define W_IMG 512
#define H_IMG 512
#define CCH   3
#define BATCH 32
#define KSZ   32
#define PAD_LO 15            // SAME padding, even kernel: lo=15, hi=16

#define MTILE 128            // y-pixels per CTA (GEMM M)
#define NTH   128            // 4 warps
#define YTILES (H_IMG / MTILE)                // 4
#define NBLOCKS (YTILES * W_IMG * CCH)        // 6144
#define N_PRED ((size_t)BATCH * W_IMG * H_IMG * CCH)

// smem union (u32 units):
//   staging buf p: raw[160] tf32 @ RAW_OFF(p),
//                  B tf32 n-major [32 b rows x pitch 36] @ B_OFF(p)
//   epilogue:      s_d [32 n x pitch 132] floats, reuses same storage
#define RAWLEN 160
#define BPITCH 36            // pitch ≡ 4 (mod 32): conflict-free frag loads AND stores
#define BUFLEN (RAWLEN + BATCH * BPITCH)   // 1312
#define RAW_OFF(p) ((p) * BUFLEN)
#define B_OFF(p)   ((p) * BUFLEN + RAWLEN)
#define DPITCH 132
#define SMEM_U32 (BATCH * DPITCH)          // 4224 >= 2*BUFLEN (2624)

__device__ double       g_partials[NBLOCKS];
__device__ unsigned int g_done = 0;

static __device__ __forceinline__ uint32_t f2tf(float v) {
    uint32_t r;
    asm("cvt.rna.tf32.f32 %0, %1;" : "=r"(r) : "f"(v));
    return r;
}

// D(16x8,f32) += A(16x8,tf32,row) * B(8x8,tf32,col)
static __device__ __forceinline__ void mma_tf32(float* d,
                                                uint32_t a0, uint32_t a1,
                                                uint32_t a2, uint32_t a3,
                                                uint32_t b0, uint32_t b1) {
    asm volatile(
        "mma.sync.aligned.m16n8k8.row.col.f32.tf32.tf32.f32 "
        "{%0,%1,%2,%3}, {%4,%5,%6,%7}, {%8,%9}, {%0,%1,%2,%3};"
        : "+f"(d[0]), "+f"(d[1]), "+f"(d[2]), "+f"(d[3])
        : "r"(a0), "r"(a1), "r"(a2), "r"(a3), "r"(b0), "r"(b1));
}

__global__ __launch_bounds__(NTH)
void conv_mma_kernel(const float* __restrict__ img,
                     const float* __restrict__ psf,
                     const float* __restrict__ obs,
                     float* __restrict__ out,
                     long long loss_idx)
{
    __shared__ uint32_t s_u[SMEM_U32];
    __shared__ float  s_red[NTH / 32];
    __shared__ double s_dred[NTH / 32];
    __shared__ int    s_last;

    const int tid   = threadIdx.x;
    const int wid   = tid >> 5;
    const int lane  = tid & 31;
    const int ytile = blockIdx.x;
    const int x     = blockIdx.y;
    const int c     = blockIdx.z;
    const int y0    = ytile * MTILE;

    const int g  = lane >> 2;        // fragment row
    const int t4 = lane & 3;         // fragment col/k

    // accumulators: warp w owns rows [32w, 32w+32), all 32 batches
    float d[2][4][4];
#pragma unroll
    for (int mt = 0; mt < 2; ++mt)
#pragma unroll
        for (int nt = 0; nt < 4; ++nt)
#pragma unroll
            for (int i = 0; i < 4; ++i) d[mt][nt][i] = 0.f;

    // ---- staging load (gmem -> regs) for PSF row r ----
    float rv0, rv1, bv[8];
    auto load_stage = [&](int r) {
        const int gx = x + r - PAD_LO;
        rv0 = 0.f; rv1 = 0.f;
        if ((unsigned)gx < W_IMG) {
            const float* rowp = img + ((size_t)gx * H_IMG) * CCH + c;
            int gy0 = y0 - PAD_LO + tid;
            int gy1 = gy0 + NTH;
            if ((unsigned)gy0 < H_IMG) rv0 = rowp[(size_t)gy0 * CCH];
            if (tid + NTH < RAWLEN && (unsigned)gy1 < H_IMG)
                rv1 = rowp[(size_t)gy1 * CCH];
        }
        // coalesced: e consecutive within warp -> one b row, s = lane
#pragma unroll
        for (int j = 0; j < 8; ++j) {
            int e = tid + j * NTH;
            int b = e >> 5, s = e & 31;
            bv[j] = psf[((size_t)(b * KSZ + r) * KSZ + s) * CCH + c];
        }
    };
    // ---- staging store (regs -> smem, tf32) into buffer p ----
    auto store_stage = [&](int p) {
        uint32_t* raw = s_u + RAW_OFF(p);
        uint32_t* Bs  = s_u + B_OFF(p);
        raw[tid] = f2tf(rv0);
        if (tid + NTH < RAWLEN) raw[tid + NTH] = f2tf(rv1);
#pragma unroll
        for (int j = 0; j < 8; ++j) {
            int e = tid + j * NTH;
            int b = e >> 5, s = e & 31;
            Bs[b * BPITCH + s] = f2tf(bv[j]);   // n-major: conflict-free STS
        }
    };

    load_stage(0);
    store_stage(0);
    __syncthreads();

    const int abase = 32 * wid + g + t4;

    // ---------------- main loop over PSF rows ----------------
#pragma unroll 1
    for (int r = 0; r < KSZ; ++r) {
        if (r + 1 < KSZ) load_stage(r + 1);     // LDGs early

        const uint32_t* raw = s_u + RAW_OFF(r & 1);
        const uint32_t* Bs  = s_u + B_OFF(r & 1);

        // Toeplitz A register cache: 14 distinct words cover all fragments
        uint32_t rv[14];
#pragma unroll
        for (int t = 0; t < 14; ++t) rv[t] = raw[abase + 4 * t];

#pragma unroll
        for (int k8 = 0; k8 < 4; ++k8) {
            uint32_t b0[4], b1[4];
#pragma unroll
            for (int nt = 0; nt < 4; ++nt) {
                // (k = k8*8 + t4 (+4), n = nt*8 + g); banks 4g+t4+8k8: conflict-free
                const int off = (nt * 8 + g) * BPITCH + k8 * 8 + t4;
                b0[nt] = Bs[off];
                b1[nt] = Bs[off + 4];
            }
#pragma unroll
            for (int mt = 0; mt < 2; ++mt) {
                const int t0 = 4 * mt + 2 * k8;
                const uint32_t a0 = rv[t0];       // raw[abase + k8*8 + mt*16]
                const uint32_t a1 = rv[t0 + 2];   // +8
                const uint32_t a2 = rv[t0 + 1];   // +4
                const uint32_t a3 = rv[t0 + 3];   // +12
#pragma unroll
                for (int nt = 0; nt < 4; ++nt)
                    mma_tf32(d[mt][nt], a0, a1, a2, a3, b0[nt], b1[nt]);
            }
        }

        if (r + 1 < KSZ) store_stage((r + 1) & 1);
        __syncthreads();
    }

    // ---------------- epilogue: D -> smem transpose -> gmem + loss ----------------
#pragma unroll
    for (int mt = 0; mt < 2; ++mt)
#pragma unroll
        for (int nt = 0; nt < 4; ++nt)
#pragma unroll
            for (int i = 0; i < 4; ++i) {
                const int n = nt * 8 + 2 * t4 + (i & 1);
                const int y = 32 * wid + 16 * mt + g + ((i >> 1) ? 8 : 0);
                s_u[n * DPITCH + y] = __float_as_uint(d[mt][nt][i]);
            }
    __syncthreads();

    // thread -> (batch b = tid/4, y-quarter q = tid%4), 32 consecutive y each
    const int bb = tid >> 2;
    const int yq = tid & 3;
    const uint32_t* drow = s_u + bb * DPITCH + yq * 32;
    const size_t obase =
        ((size_t)((size_t)bb * W_IMG + x) * H_IMG + (y0 + yq * 32)) * CCH + c;
    float lsum = 0.f;
#pragma unroll
    for (int i = 0; i < 32; ++i) {
        float p = __uint_as_float(drow[i]);
        size_t idx = obase + (size_t)i * CCH;
        out[idx] = p;
        float dd = obs[idx] - p;
        lsum += dd * dd;
    }

    // block reduce loss
#pragma unroll
    for (int off = 16; off; off >>= 1)
        lsum += __shfl_xor_sync(0xffffffffu, lsum, off);
    if (lane == 0) s_red[wid] = lsum;
    __syncthreads();

    const int lin = ytile + YTILES * (x + W_IMG * c);
    if (tid == 0) {
        float bsum = 0.f;
#pragma unroll
        for (int w = 0; w < NTH / 32; ++w) bsum += s_red[w];
        g_partials[lin] = (double)bsum;
        __threadfence();
        unsigned prev = atomicAdd(&g_done, 1u);
        s_last = (prev == NBLOCKS - 1);
    }
    __syncthreads();

    if (s_last) {
        double dsum = 0.0;
        for (int i = tid; i < NBLOCKS; i += NTH) dsum += g_partials[i];
#pragma unroll
        for (int off = 16; off; off >>= 1)
            dsum += __shfl_xor_sync(0xffffffffu, dsum, off);
        if (lane == 0) s_dred[wid] = dsum;
        __syncthreads();
        if (tid == 0) {
            double tot = 0.0;
#pragma unroll
            for (int w = 0; w < NTH / 32; ++w) tot += s_dred[w];
            out[loss_idx] = (float)(tot / (double)N_PRED);
            g_done = 0;   // self-reset: deterministic across graph replays
        }
    }
}

extern "C" void kernel_launch(void* const* d_in, const int* in_sizes, int n_in,
                              void* d_out, int out_size) {
    const float* obs = nullptr;
    const float* img = nullptr;
    const float* psf = nullptr;
    for (int i = 0; i < n_in; ++i) {
        long long n = in_sizes[i];
        if (n == (long long)BATCH * W_IMG * H_IMG * CCH)      obs = (const float*)d_in[i];
        else if (n == (long long)W_IMG * H_IMG * CCH)         img = (const float*)d_in[i];
        else if (n == (long long)BATCH * KSZ * KSZ * CCH)     psf = (const float*)d_in[i];
    }
    float* out = (float*)d_out;

    dim3 grid(YTILES, W_IMG, CCH);   // 6144 CTAs
    conv_mma_kernel<<<grid, NTH>>>(img, psf, obs, out, (long long)out_size - 1);
}

// round 11
// speedup vs baseline: 1.5399x; 1.2106x over previous
#include <cuda_runtime.h>
#include <cstdint>

// ---------------- problem constants ----------------
#define W_IMG 512
#define H_IMG 512
#define CCH   3
#define BATCH 32
#define KSZ   32
#define PAD_LO 15            // SAME padding, even kernel: lo=15, hi=16
#define XPAD  544            // 15 + 512 + 17 (halo baked into packed image)

#define MTILE 128            // y-pixels per CTA (GEMM M)
#define NTH   128            // 4 warps
#define YTILES (H_IMG / MTILE)                // 4
#define NBLOCKS (YTILES * W_IMG * CCH)        // 6144
#define N_PRED ((size_t)BATCH * W_IMG * H_IMG * CCH)

// smem union (u32 units):
//   staging buf p: raw[160] tf32 @ RAW_OFF(p),
//                  B tf32 n-major [32 b rows x pitch 36] @ B_OFF(p)
//   epilogue:      s_d [32 n x pitch 132] floats, reuses same storage
#define RAWLEN 160
#define BPITCH 36            // pitch ≡ 4 (mod 32): conflict-free frag loads
#define BUFLEN (RAWLEN + BATCH * BPITCH)   // 1312
#define RAW_OFF(p) ((p) * BUFLEN)
#define B_OFF(p)   ((p) * BUFLEN + RAWLEN)
#define DPITCH 132
#define SMEM_U32 (BATCH * DPITCH)          // 4224 >= 2*BUFLEN (2624)

__device__ double       g_partials[NBLOCKS];
__device__ unsigned int g_done = 0;
// packed, tf32-converted, zero-padded scratch (static device arrays: legal)
__device__ __align__(16) uint32_t g_img_packed[CCH * XPAD * XPAD];          // 3.55 MB
__device__ __align__(16) uint32_t g_psf_packed[CCH * KSZ * BATCH * KSZ];    // 393 KB

static __device__ __forceinline__ uint32_t f2tf(float v) {
    uint32_t r;
    asm("cvt.rna.tf32.f32 %0, %1;" : "=r"(r) : "f"(v));
    return r;
}
static __device__ __forceinline__ uint32_t smem_u32(const void* p) {
    uint32_t a;
    asm("{ .reg .u64 t; cvta.to.shared.u64 t, %1; cvt.u32.u64 %0, t; }"
        : "=r"(a) : "l"(p));
    return a;
}
static __device__ __forceinline__ void cp_async16(uint32_t dst, const void* src) {
    asm volatile("cp.async.cg.shared.global [%0], [%1], 16;"
                 :: "r"(dst), "l"(src) : "memory");
}

// D(16x8,f32) += A(16x8,tf32,row) * B(8x8,tf32,col)
static __device__ __forceinline__ void mma_tf32(float* d,
                                                uint32_t a0, uint32_t a1,
                                                uint32_t a2, uint32_t a3,
                                                uint32_t b0, uint32_t b1) {
    asm volatile(
        "mma.sync.aligned.m16n8k8.row.col.f32.tf32.tf32.f32 "
        "{%0,%1,%2,%3}, {%4,%5,%6,%7}, {%8,%9}, {%0,%1,%2,%3};"
        : "+f"(d[0]), "+f"(d[1]), "+f"(d[2]), "+f"(d[3])
        : "r"(a0), "r"(a1), "r"(a2), "r"(a3), "r"(b0), "r"(b1));
}

// ---------------- pack pre-pass ----------------
__global__ void pack_kernel(const float* __restrict__ img,
                            const float* __restrict__ psf) {
    const int stride = gridDim.x * blockDim.x;
    const int n_img = CCH * XPAD * XPAD;
    for (int i = blockIdx.x * blockDim.x + threadIdx.x; i < n_img; i += stride) {
        int c   = i / (XPAD * XPAD);
        int rem = i - c * XPAD * XPAD;
        int X = rem / XPAD, Y = rem - (rem / XPAD) * XPAD;
        int gx = X - PAD_LO, gy = Y - PAD_LO;
        uint32_t v = 0u;
        if ((unsigned)gx < W_IMG && (unsigned)gy < H_IMG)
            v = f2tf(img[((size_t)gx * H_IMG + gy) * CCH + c]);
        g_img_packed[i] = v;
    }
    const int n_psf = CCH * KSZ * BATCH * KSZ;
    for (int i = blockIdx.x * blockDim.x + threadIdx.x; i < n_psf; i += stride) {
        int c    = i / (KSZ * BATCH * KSZ);
        int rem  = i - c * (KSZ * BATCH * KSZ);
        int r    = rem / (BATCH * KSZ);
        int rem2 = rem - r * (BATCH * KSZ);
        int b = rem2 >> 5, s = rem2 & 31;
        g_psf_packed[i] = f2tf(psf[((size_t)(b * KSZ + r) * KSZ + s) * CCH + c]);
    }
}

// ---------------- main kernel ----------------
__global__ __launch_bounds__(NTH, 6)
void conv_mma_kernel(const float* __restrict__ obs,
                     float* __restrict__ out,
                     long long loss_idx)
{
    __shared__ __align__(16) uint32_t s_u[SMEM_U32];
    __shared__ float  s_red[NTH / 32];
    __shared__ double s_dred[NTH / 32];
    __shared__ int    s_last;

    const int tid   = threadIdx.x;
    const int wid   = tid >> 5;
    const int lane  = tid & 31;
    const int ytile = blockIdx.x;
    const int x     = blockIdx.y;
    const int c     = blockIdx.z;
    const int y0    = ytile * MTILE;

    const int g  = lane >> 2;        // fragment row
    const int t4 = lane & 3;         // fragment col/k

    float d[2][4][4];
#pragma unroll
    for (int mt = 0; mt < 2; ++mt)
#pragma unroll
        for (int nt = 0; nt < 4; ++nt)
#pragma unroll
            for (int i = 0; i < 4; ++i) d[mt][nt][i] = 0.f;

    const uint32_t su = smem_u32(s_u);

    // async stage of PSF row r into buffer p (tf32 bits, pre-padded)
    auto stage_async = [&](int r, int p) {
        // raw image row: 160 contiguous tf32 words (halo pre-baked, no guards)
        const uint32_t* src_raw =
            g_img_packed + ((size_t)(c * XPAD + (x + r))) * XPAD + y0;
        if (tid < RAWLEN / 4)
            cp_async16(su + (uint32_t)(RAW_OFF(p) + tid * 4) * 4,
                       src_raw + tid * 4);
        // B tile: 4KB contiguous -> scattered dst rows of pitch 36
        const uint32_t* src_b =
            g_psf_packed + ((size_t)(c * KSZ + r) * BATCH) * KSZ;
#pragma unroll
        for (int j = 0; j < 2; ++j) {
            int e = tid + j * NTH;          // 16B-chunk id: b = e/8, s4 = e%8
            int b = e >> 3, s4 = e & 7;
            cp_async16(su + (uint32_t)(B_OFF(p) + b * BPITCH + s4 * 4) * 4,
                       src_b + b * KSZ + s4 * 4);
        }
        asm volatile("cp.async.commit_group;" ::: "memory");
    };

    stage_async(0, 0);
    asm volatile("cp.async.wait_group 0;" ::: "memory");
    __syncthreads();

    const int abase = 32 * wid + g + t4;

#pragma unroll 1
    for (int r = 0; r < KSZ; ++r) {
        if (r + 1 < KSZ) stage_async(r + 1, (r + 1) & 1);

        const uint32_t* raw = s_u + RAW_OFF(r & 1);
        const uint32_t* Bs  = s_u + B_OFF(r & 1);

        // Toeplitz A register cache: 14 distinct words cover all fragments
        uint32_t rv[14];
#pragma unroll
        for (int t = 0; t < 14; ++t) rv[t] = raw[abase + 4 * t];

#pragma unroll
        for (int k8 = 0; k8 < 4; ++k8) {
            uint32_t b0[4], b1[4];
#pragma unroll
            for (int nt = 0; nt < 4; ++nt) {
                const int off = (nt * 8 + g) * BPITCH + k8 * 8 + t4;
                b0[nt] = Bs[off];
                b1[nt] = Bs[off + 4];
            }
#pragma unroll
            for (int mt = 0; mt < 2; ++mt) {
                const int t0 = 4 * mt + 2 * k8;
                const uint32_t a0 = rv[t0];
                const uint32_t a1 = rv[t0 + 2];
                const uint32_t a2 = rv[t0 + 1];
                const uint32_t a3 = rv[t0 + 3];
#pragma unroll
                for (int nt = 0; nt < 4; ++nt)
                    mma_tf32(d[mt][nt], a0, a1, a2, a3, b0[nt], b1[nt]);
            }
        }

        asm volatile("cp.async.wait_group 0;" ::: "memory");
        __syncthreads();
    }

    // ---------------- epilogue: D -> smem transpose -> gmem + loss ----------------
#pragma unroll
    for (int mt = 0; mt < 2; ++mt)
#pragma unroll
        for (int nt = 0; nt < 4; ++nt)
#pragma unroll
            for (int i = 0; i < 4; ++i) {
                const int n = nt * 8 + 2 * t4 + (i & 1);
                const int y = 32 * wid + 16 * mt + g + ((i >> 1) ? 8 : 0);
                s_u[n * DPITCH + y] = __float_as_uint(d[mt][nt][i]);
            }
    __syncthreads();

    const int bb = tid >> 2;
    const int yq = tid & 3;
    const uint32_t* drow = s_u + bb * DPITCH + yq * 32;
    const size_t obase =
        ((size_t)((size_t)bb * W_IMG + x) * H_IMG + (y0 + yq * 32)) * CCH + c;
    float lsum = 0.f;
#pragma unroll
    for (int i = 0; i < 32; ++i) {
        float p = __uint_as_float(drow[i]);
        size_t idx = obase + (size_t)i * CCH;
        out[idx] = p;
        float dd = obs[idx] - p;
        lsum += dd * dd;
    }

#pragma unroll
    for (int off = 16; off; off >>= 1)
        lsum += __shfl_xor_sync(0xffffffffu, lsum, off);
    if (lane == 0) s_red[wid] = lsum;
    __syncthreads();

    const int lin = ytile + YTILES * (x + W_IMG * c);
    if (tid == 0) {
        float bsum = 0.f;
#pragma unroll
        for (int w = 0; w < NTH / 32; ++w) bsum += s_red[w];
        g_partials[lin] = (double)bsum;
        __threadfence();
        unsigned prev = atomicAdd(&g_done, 1u);
        s_last = (prev == NBLOCKS - 1);
    }
    __syncthreads();

    if (s_last) {
        double dsum = 0.0;
        for (int i = tid; i < NBLOCKS; i += NTH) dsum += g_partials[i];
#pragma unroll
        for (int off = 16; off; off >>= 1)
            dsum += __shfl_xor_sync(0xffffffffu, dsum, off);
        if (lane == 0) s_dred[wid] = dsum;
        __syncthreads();
        if (tid == 0) {
            double tot = 0.0;
#pragma unroll
            for (int w = 0; w < NTH / 32; ++w) tot += s_dred[w];
            out[loss_idx] = (float)(tot / (double)N_PRED);
            g_done = 0;   // self-reset: deterministic across graph replays
        }
    }
}

extern "C" void kernel_launch(void* const* d_in, const int* in_sizes, int n_in,
                              void* d_out, int out_size) {
    const float* obs = nullptr;
    const float* img = nullptr;
    const float* psf = nullptr;
    for (int i = 0; i < n_in; ++i) {
        long long n = in_sizes[i];
        if (n == (long long)BATCH * W_IMG * H_IMG * CCH)      obs = (const float*)d_in[i];
        else if (n == (long long)W_IMG * H_IMG * CCH)         img = (const float*)d_in[i];
        else if (n == (long long)BATCH * KSZ * KSZ * CCH)     psf = (const float*)d_in[i];
    }
    float* out = (float*)d_out;

    pack_kernel<<<1024, 256>>>(img, psf);
    dim3 grid(YTILES, W_IMG, CCH);   // 6144 CTAs
    conv_mma_kernel<<<grid, NTH>>>(obs, out, (long long)out_size - 1);
}